// round 15
// baseline (speedup 1.0000x reference)
#include <cuda_runtime.h>
#include <cuda_fp16.h>
#include <cstdint>

#define N_NODES 50000
#define N_EDGES 1600000
#define D_FEAT  128
#define NH4     (D_FEAT / 8)   // 16 uint4 (8 halfs) per fp16 row

#define SCAN_CHUNK   1024
#define SCAN_BLOCKS  ((N_NODES + SCAN_CHUNK - 1) / SCAN_CHUNK)   // 49

// Scratch (no cudaMalloc allowed).
__device__ uint4 g_xh      [(size_t)N_NODES * NH4];   // fp16 copy of gather operand
__device__ uint4 g_scratchh[(size_t)N_NODES * NH4];   // fp16 round-1 result
__device__ int   g_counts  [N_NODES];                 // zero at every call entry
__device__ int   g_row_ptr [N_NODES + 1];             // chunk-local exclusive scan
__device__ int   g_cursor  [N_NODES];                 // chunk-local, consumed by scatter
__device__ int2  g_edges   [N_EDGES];                 // packed (col, val-bits)
__device__ int   g_partials[SCAN_BLOCKS];             // per-chunk totals

// ---- packed f32x2 helpers (sm_103a FFMA2 path) ------------------------------
__device__ __forceinline__ unsigned long long pack2(float a, float b) {
    unsigned long long p;
    asm("mov.b64 %0, {%1, %2};" : "=l"(p) : "f"(a), "f"(b));
    return p;
}
__device__ __forceinline__ void fma2(unsigned long long& acc,
                                     unsigned long long ab,
                                     unsigned long long v2) {
    asm("fma.rn.f32x2 %0, %1, %2, %0;" : "+l"(acc) : "l"(ab), "l"(v2));
}
__device__ __forceinline__ void unpack2(unsigned long long p, float& a, float& b) {
    asm("mov.b64 {%0, %1}, %2;" : "=f"(a), "=f"(b) : "l"(p));
}

// ---- per-block inline exclusive scan of the 49 chunk totals into SMEM ------
__device__ __forceinline__ void block_scan_partials(
    const int* __restrict__ partials, int* s_poffs, int* s_wsum)
{
    const int tid = threadIdx.x;
    int p_incl = 0, p_v = 0;
    if (tid < 64) {
        const int lane = tid & 31;
        p_v = (tid < SCAN_BLOCKS) ? __ldg(partials + tid) : 0;
        p_incl = p_v;
        #pragma unroll
        for (int off = 1; off < 32; off <<= 1) {
            int t = __shfl_up_sync(0xffffffffu, p_incl, off);
            if (lane >= off) p_incl += t;
        }
        if (lane == 31) s_wsum[tid >> 5] = p_incl;
    }
    __syncthreads();
    if (tid < SCAN_BLOCKS) {
        int wadd = (tid >= 32) ? s_wsum[0] : 0;
        s_poffs[tid] = p_incl - p_v + wadd;
    }
    __syncthreads();
}

// -------- fused hist + fp32->fp16 conversion (independent work, one launch) --
__global__ void __launch_bounds__(256) hist_conv_kernel(
    const int4* __restrict__ adj_row4, int* __restrict__ counts,
    int n_q, int n_edges, const int* __restrict__ adj_row,
    int histB,
    const float4* __restrict__ xin, uint4* __restrict__ xh, int nconv)
{
    if ((int)blockIdx.x < histB) {
        int q = blockIdx.x * blockDim.x + threadIdx.x;
        if (q < n_q) {
            int4 r = __ldg(adj_row4 + q);
            atomicAdd(&counts[r.x], 1);     // no return -> RED
            atomicAdd(&counts[r.y], 1);
            atomicAdd(&counts[r.z], 1);
            atomicAdd(&counts[r.w], 1);
        } else if (q == n_q) {              // tail (n_edges % 4 != 0)
            for (int e = n_q * 4; e < n_edges; e++)
                atomicAdd(&counts[adj_row[e]], 1);
        }
    } else {
        int i = (blockIdx.x - histB) * blockDim.x + threadIdx.x;
        if (i >= nconv) return;
        float4 f0 = xin[2 * i];
        float4 f1 = xin[2 * i + 1];
        __half2 h0 = __float22half2_rn(make_float2(f0.x, f0.y));
        __half2 h1 = __float22half2_rn(make_float2(f0.z, f0.w));
        __half2 h2 = __float22half2_rn(make_float2(f1.x, f1.y));
        __half2 h3 = __float22half2_rn(make_float2(f1.z, f1.w));
        uint4 o;
        o.x = *reinterpret_cast<unsigned*>(&h0);
        o.y = *reinterpret_cast<unsigned*>(&h1);
        o.z = *reinterpret_cast<unsigned*>(&h2);
        o.w = *reinterpret_cast<unsigned*>(&h3);
        xh[i] = o;
    }
}

// Chunk-local exclusive scan; restores counts to zero; writes row_ptr, cursor.
__global__ void __launch_bounds__(1024) scan_block_kernel(
    int* __restrict__ counts, int* __restrict__ row_ptr,
    int* __restrict__ cursor, int* __restrict__ partials)
{
    __shared__ int warp_sums[32];
    const int tid  = threadIdx.x;
    const int lane = tid & 31;
    const int wid  = tid >> 5;
    const int i    = blockIdx.x * SCAN_CHUNK + tid;

    int v = 0;
    if (i < N_NODES) {
        v = counts[i];
        counts[i] = 0;          // restore invariant
    }

    int incl = v;
    #pragma unroll
    for (int off = 1; off < 32; off <<= 1) {
        int t = __shfl_up_sync(0xffffffffu, incl, off);
        if (lane >= off) incl += t;
    }
    if (lane == 31) warp_sums[wid] = incl;
    __syncthreads();

    if (wid == 0) {
        int s = warp_sums[lane];
        int si = s;
        #pragma unroll
        for (int off = 1; off < 32; off <<= 1) {
            int t = __shfl_up_sync(0xffffffffu, si, off);
            if (lane >= off) si += t;
        }
        warp_sums[lane] = si - s;
    }
    __syncthreads();

    int excl = incl - v + warp_sums[wid];
    if (i <= N_NODES) row_ptr[i] = excl;                // includes i == N_NODES
    if (i < N_NODES)  cursor[i]  = excl;                // scatter's working copy
    if (tid == SCAN_CHUNK - 1) partials[blockIdx.x] = excl + v;
}

// Place packed (col, val). Slot from cursor atomic (chunk-local) + s_poffs.
__global__ void __launch_bounds__(256) scatter_kernel(
    const int4* __restrict__ adj_row4,
    const int4* __restrict__ adj_col4,
    const float4* __restrict__ adj_vals4,
    int* __restrict__ cursor,
    const int* __restrict__ partials,
    int2* __restrict__ edges,
    int n_q, int n_edges,
    const int* __restrict__ adj_row,
    const int* __restrict__ adj_col,
    const float* __restrict__ adj_vals)
{
    __shared__ int s_poffs[SCAN_BLOCKS];
    __shared__ int s_wsum[2];
    block_scan_partials(partials, s_poffs, s_wsum);

    int q = blockIdx.x * blockDim.x + threadIdx.x;
    if (q < n_q) {
        int4   r = __ldg(adj_row4  + q);
        int4   c = __ldg(adj_col4  + q);
        float4 v = __ldg(adj_vals4 + q);
        int p0 = atomicAdd(&cursor[r.x], 1);
        int p1 = atomicAdd(&cursor[r.y], 1);
        int p2 = atomicAdd(&cursor[r.z], 1);
        int p3 = atomicAdd(&cursor[r.w], 1);
        edges[p0 + s_poffs[r.x >> 10]] = make_int2(c.x, __float_as_int(v.x));
        edges[p1 + s_poffs[r.y >> 10]] = make_int2(c.y, __float_as_int(v.y));
        edges[p2 + s_poffs[r.z >> 10]] = make_int2(c.z, __float_as_int(v.z));
        edges[p3 + s_poffs[r.w >> 10]] = make_int2(c.w, __float_as_int(v.w));
    } else if (q == n_q) {            // tail
        for (int e = n_q * 4; e < n_edges; e++) {
            int r = adj_row[e];
            int p = atomicAdd(&cursor[r], 1) + s_poffs[r >> 10];
            edges[p] = make_int2(adj_col[e], __float_as_int(adj_vals[e]));
        }
    }
}

// ---------------- CSR SpMM: warp/row, half-warp/edge, fp16 gather ------------
// Guard-free strips: pad lanes carry (col=0, val=0) -> zero-weight gather of
// row 0 (same address across pad lanes, L1-hot). Inner loop fully unrolled.
// Accumulation via packed fma.rn.f32x2 (exact fp32 math, half the FFMA count).
template <int OUT_HALF>
__global__ void __launch_bounds__(256) spmm_csr_h_kernel(
    const uint4* __restrict__ xh,
    const int*   __restrict__ row_ptr,
    const int*   __restrict__ partials,
    const int2*  __restrict__ edges,
    void*        __restrict__ out)
{
    __shared__ int s_poffs[SCAN_BLOCKS];
    __shared__ int s_wsum[2];
    block_scan_partials(partials, s_poffs, s_wsum);

    int row  = (blockIdx.x * blockDim.x + threadIdx.x) >> 5;
    int lane = threadIdx.x & 31;
    if (row >= N_NODES) return;

    const int hlane = lane & 15;
    const int half  = lane >> 4;

    int start = __ldg(row_ptr + row)     + s_poffs[row >> 10];
    int end   = __ldg(row_ptr + row + 1) + s_poffs[(row + 1) >> 10];

    unsigned long long acc0 = 0, acc1 = 0, acc2 = 0, acc3 = 0;
    const uint4* xb = xh + hlane;

    for (int base = start; base < end; base += 32) {
        int2 ep = make_int2(0, 0);
        if (base + lane < end) ep = __ldg(edges + base + lane);

        #pragma unroll
        for (int j = 0; j < 32; j += 2) {
            int je = j + half;
            int cj = __shfl_sync(0xffffffffu, ep.x, je);
            int vb = __shfl_sync(0xffffffffu, ep.y, je);
            float vj = __int_as_float(vb);
            unsigned long long vj2 = pack2(vj, vj);

            uint4 m = __ldg(xb + (size_t)cj * NH4);
            float2 f0 = __half22float2(*reinterpret_cast<__half2*>(&m.x));
            float2 f1 = __half22float2(*reinterpret_cast<__half2*>(&m.y));
            float2 f2 = __half22float2(*reinterpret_cast<__half2*>(&m.z));
            float2 f3 = __half22float2(*reinterpret_cast<__half2*>(&m.w));
            fma2(acc0, pack2(f0.x, f0.y), vj2);
            fma2(acc1, pack2(f1.x, f1.y), vj2);
            fma2(acc2, pack2(f2.x, f2.y), vj2);
            fma2(acc3, pack2(f3.x, f3.y), vj2);
        }
    }

    float a[8];
    unpack2(acc0, a[0], a[1]);
    unpack2(acc1, a[2], a[3]);
    unpack2(acc2, a[4], a[5]);
    unpack2(acc3, a[6], a[7]);

    #pragma unroll
    for (int k = 0; k < 8; k++)
        a[k] += __shfl_xor_sync(0xffffffffu, a[k], 16);

    if (half == 0) {
        if (OUT_HALF) {
            __half2 h0 = __float22half2_rn(make_float2(a[0], a[1]));
            __half2 h1 = __float22half2_rn(make_float2(a[2], a[3]));
            __half2 h2 = __float22half2_rn(make_float2(a[4], a[5]));
            __half2 h3 = __float22half2_rn(make_float2(a[6], a[7]));
            uint4 o;
            o.x = *reinterpret_cast<unsigned*>(&h0);
            o.y = *reinterpret_cast<unsigned*>(&h1);
            o.z = *reinterpret_cast<unsigned*>(&h2);
            o.w = *reinterpret_cast<unsigned*>(&h3);
            reinterpret_cast<uint4*>(out)[(size_t)row * NH4 + hlane] = o;
        } else {
            float4* o4 = reinterpret_cast<float4*>(out) + (size_t)row * (D_FEAT / 4) + hlane * 2;
            o4[0] = make_float4(a[0], a[1], a[2], a[3]);
            o4[1] = make_float4(a[4], a[5], a[6], a[7]);
        }
    }
}

// ---------------- launch ----------------
extern "C" void kernel_launch(void* const* d_in, const int* in_sizes, int n_in,
                              void* d_out, int out_size) {
    const float* x        = (const float*)d_in[0];
    const int*   adj_row  = (const int*)  d_in[1];
    const int*   adj_col  = (const int*)  d_in[2];
    const float* adj_vals = (const float*)d_in[3];
    float*       out      = (float*)d_out;

    int n_edges = in_sizes[1];
    int n_q = n_edges / 4;             // int4 quads

    uint4 *xh, *scratchh; int *counts, *row_ptr, *cursor, *partials; int2 *edges;
    cudaGetSymbolAddress((void**)&xh,       g_xh);
    cudaGetSymbolAddress((void**)&scratchh, g_scratchh);
    cudaGetSymbolAddress((void**)&counts,   g_counts);
    cudaGetSymbolAddress((void**)&row_ptr,  g_row_ptr);
    cudaGetSymbolAddress((void**)&cursor,   g_cursor);
    cudaGetSymbolAddress((void**)&partials, g_partials);
    cudaGetSymbolAddress((void**)&edges,    g_edges);

    const int T = 256;
    const int histB = (n_q + 1 + T - 1) / T;   // +1 thread for the tail
    const int nconv = N_NODES * NH4;
    const int convB = (nconv + T - 1) / T;

    // Fused: histogram (RED) + fp16 conversion. counts zero at entry.
    hist_conv_kernel<<<histB + convB, T>>>((const int4*)adj_row, counts,
                                           n_q, n_edges, adj_row, histB,
                                           (const float4*)x, xh, nconv);

    scan_block_kernel<<<SCAN_BLOCKS, SCAN_CHUNK>>>(counts, row_ptr, cursor, partials);

    scatter_kernel<<<histB, T>>>((const int4*)adj_row, (const int4*)adj_col,
                                 (const float4*)adj_vals, cursor, partials,
                                 edges, n_q, n_edges,
                                 adj_row, adj_col, adj_vals);

    // Two propagation rounds.
    const int WPB = T / 32;
    const int sb = (N_NODES + WPB - 1) / WPB;
    spmm_csr_h_kernel<1><<<sb, T>>>(xh, row_ptr, partials, edges, scratchh);
    spmm_csr_h_kernel<0><<<sb, T>>>(scratchh, row_ptr, partials, edges, out);
}

// round 16
// speedup vs baseline: 1.0321x; 1.0321x over previous
#include <cuda_runtime.h>
#include <cuda_fp16.h>
#include <cstdint>

#define N_NODES 50000
#define N_EDGES 1600000
#define D_FEAT  128
#define NH4     (D_FEAT / 8)   // 16 uint4 (8 halfs) per fp16 row

#define SCAN_CHUNK   1024
#define SCAN_BLOCKS  ((N_NODES + SCAN_CHUNK - 1) / SCAN_CHUNK)   // 49

// Scratch (no cudaMalloc allowed).
__device__ uint4 g_xh      [(size_t)N_NODES * NH4];   // fp16 copy of gather operand
__device__ uint4 g_scratchh[(size_t)N_NODES * NH4];   // fp16 round-1 result
__device__ int   g_counts  [N_NODES];                 // zero at every call entry
__device__ int   g_row_ptr [N_NODES + 1];             // chunk-local exclusive scan
__device__ int   g_cursor  [N_NODES];                 // chunk-local, consumed by scatter
__device__ int2  g_edges   [N_EDGES];                 // packed (col byte-offset, val-bits)
__device__ int   g_partials[SCAN_BLOCKS];             // per-chunk totals

// ---- per-block inline exclusive scan of the 49 chunk totals into SMEM ------
__device__ __forceinline__ void block_scan_partials(
    const int* __restrict__ partials, int* s_poffs, int* s_wsum)
{
    const int tid = threadIdx.x;
    int p_incl = 0, p_v = 0;
    if (tid < 64) {
        const int lane = tid & 31;
        p_v = (tid < SCAN_BLOCKS) ? __ldg(partials + tid) : 0;
        p_incl = p_v;
        #pragma unroll
        for (int off = 1; off < 32; off <<= 1) {
            int t = __shfl_up_sync(0xffffffffu, p_incl, off);
            if (lane >= off) p_incl += t;
        }
        if (lane == 31) s_wsum[tid >> 5] = p_incl;
    }
    __syncthreads();
    if (tid < SCAN_BLOCKS) {
        int wadd = (tid >= 32) ? s_wsum[0] : 0;
        s_poffs[tid] = p_incl - p_v + wadd;
    }
    __syncthreads();
}

// -------- fused hist + fp32->fp16 conversion (independent work, one launch) --
__global__ void __launch_bounds__(256) hist_conv_kernel(
    const int4* __restrict__ adj_row4, int* __restrict__ counts,
    int n_q, int n_edges, const int* __restrict__ adj_row,
    int histB,
    const float4* __restrict__ xin, uint4* __restrict__ xh, int nconv)
{
    if ((int)blockIdx.x < histB) {
        int q = blockIdx.x * blockDim.x + threadIdx.x;
        if (q < n_q) {
            int4 r = __ldg(adj_row4 + q);
            atomicAdd(&counts[r.x], 1);     // no return -> RED
            atomicAdd(&counts[r.y], 1);
            atomicAdd(&counts[r.z], 1);
            atomicAdd(&counts[r.w], 1);
        } else if (q == n_q) {              // tail (n_edges % 4 != 0)
            for (int e = n_q * 4; e < n_edges; e++)
                atomicAdd(&counts[adj_row[e]], 1);
        }
    } else {
        int i = (blockIdx.x - histB) * blockDim.x + threadIdx.x;
        if (i >= nconv) return;
        float4 f0 = xin[2 * i];
        float4 f1 = xin[2 * i + 1];
        __half2 h0 = __float22half2_rn(make_float2(f0.x, f0.y));
        __half2 h1 = __float22half2_rn(make_float2(f0.z, f0.w));
        __half2 h2 = __float22half2_rn(make_float2(f1.x, f1.y));
        __half2 h3 = __float22half2_rn(make_float2(f1.z, f1.w));
        uint4 o;
        o.x = *reinterpret_cast<unsigned*>(&h0);
        o.y = *reinterpret_cast<unsigned*>(&h1);
        o.z = *reinterpret_cast<unsigned*>(&h2);
        o.w = *reinterpret_cast<unsigned*>(&h3);
        xh[i] = o;
    }
}

// Chunk-local exclusive scan; restores counts to zero; writes row_ptr, cursor.
__global__ void __launch_bounds__(1024) scan_block_kernel(
    int* __restrict__ counts, int* __restrict__ row_ptr,
    int* __restrict__ cursor, int* __restrict__ partials)
{
    __shared__ int warp_sums[32];
    const int tid  = threadIdx.x;
    const int lane = tid & 31;
    const int wid  = tid >> 5;
    const int i    = blockIdx.x * SCAN_CHUNK + tid;

    int v = 0;
    if (i < N_NODES) {
        v = counts[i];
        counts[i] = 0;          // restore invariant
    }

    int incl = v;
    #pragma unroll
    for (int off = 1; off < 32; off <<= 1) {
        int t = __shfl_up_sync(0xffffffffu, incl, off);
        if (lane >= off) incl += t;
    }
    if (lane == 31) warp_sums[wid] = incl;
    __syncthreads();

    if (wid == 0) {
        int s = warp_sums[lane];
        int si = s;
        #pragma unroll
        for (int off = 1; off < 32; off <<= 1) {
            int t = __shfl_up_sync(0xffffffffu, si, off);
            if (lane >= off) si += t;
        }
        warp_sums[lane] = si - s;
    }
    __syncthreads();

    int excl = incl - v + warp_sums[wid];
    if (i <= N_NODES) row_ptr[i] = excl;                // includes i == N_NODES
    if (i < N_NODES)  cursor[i]  = excl;                // scatter's working copy
    if (tid == SCAN_CHUNK - 1) partials[blockIdx.x] = excl + v;
}

// Place packed (col byte-offset, val). Slot from cursor atomic + s_poffs.
__global__ void __launch_bounds__(256) scatter_kernel(
    const int4* __restrict__ adj_row4,
    const int4* __restrict__ adj_col4,
    const float4* __restrict__ adj_vals4,
    int* __restrict__ cursor,
    const int* __restrict__ partials,
    int2* __restrict__ edges,
    int n_q, int n_edges,
    const int* __restrict__ adj_row,
    const int* __restrict__ adj_col,
    const float* __restrict__ adj_vals)
{
    __shared__ int s_poffs[SCAN_BLOCKS];
    __shared__ int s_wsum[2];
    block_scan_partials(partials, s_poffs, s_wsum);

    int q = blockIdx.x * blockDim.x + threadIdx.x;
    if (q < n_q) {
        int4   r = __ldg(adj_row4  + q);
        int4   c = __ldg(adj_col4  + q);
        float4 v = __ldg(adj_vals4 + q);
        int p0 = atomicAdd(&cursor[r.x], 1);
        int p1 = atomicAdd(&cursor[r.y], 1);
        int p2 = atomicAdd(&cursor[r.z], 1);
        int p3 = atomicAdd(&cursor[r.w], 1);
        edges[p0 + s_poffs[r.x >> 10]] = make_int2(c.x << 8, __float_as_int(v.x));
        edges[p1 + s_poffs[r.y >> 10]] = make_int2(c.y << 8, __float_as_int(v.y));
        edges[p2 + s_poffs[r.z >> 10]] = make_int2(c.z << 8, __float_as_int(v.z));
        edges[p3 + s_poffs[r.w >> 10]] = make_int2(c.w << 8, __float_as_int(v.w));
    } else if (q == n_q) {            // tail
        for (int e = n_q * 4; e < n_edges; e++) {
            int r = adj_row[e];
            int p = atomicAdd(&cursor[r], 1) + s_poffs[r >> 10];
            edges[p] = make_int2(adj_col[e] << 8, __float_as_int(adj_vals[e]));
        }
    }
}

// ---------------- CSR SpMM: warp/row, half-warp/edge, fp16 gather ------------
// Full 32-edge strips run a guard-free fully-unrolled loop; the (<=1 per row)
// tail strip uses the guarded loop. Edge .x carries the precomputed row byte
// offset (col*256), so the gather address is a single add.
template <int OUT_HALF>
__global__ void __launch_bounds__(256) spmm_csr_h_kernel(
    const uint4* __restrict__ xh,
    const int*   __restrict__ row_ptr,
    const int*   __restrict__ partials,
    const int2*  __restrict__ edges,
    void*        __restrict__ out)
{
    __shared__ int s_poffs[SCAN_BLOCKS];
    __shared__ int s_wsum[2];
    block_scan_partials(partials, s_poffs, s_wsum);

    int row  = (blockIdx.x * blockDim.x + threadIdx.x) >> 5;
    int lane = threadIdx.x & 31;
    if (row >= N_NODES) return;

    const int hlane = lane & 15;
    const int half  = lane >> 4;

    int start = __ldg(row_ptr + row)     + s_poffs[row >> 10];
    int end   = __ldg(row_ptr + row + 1) + s_poffs[(row + 1) >> 10];

    float a0 = 0.f, a1 = 0.f, a2 = 0.f, a3 = 0.f,
          a4 = 0.f, a5 = 0.f, a6 = 0.f, a7 = 0.f;
    const char* xb = reinterpret_cast<const char*>(xh) + hlane * sizeof(uint4);

    int nfull = (end - start) & ~31;
    int base  = start;

    // ---- full strips: no guards, fully unrolled ----
    for (; base < start + nfull; base += 32) {
        int2 ep = __ldg(edges + base + lane);
        #pragma unroll
        for (int j = 0; j < 32; j += 2) {
            int   coff = __shfl_sync(0xffffffffu, ep.x, j + half);
            int   vb   = __shfl_sync(0xffffffffu, ep.y, j + half);
            float vj   = __int_as_float(vb);
            uint4 m = __ldg(reinterpret_cast<const uint4*>(xb + coff));
            float2 f0 = __half22float2(*reinterpret_cast<__half2*>(&m.x));
            float2 f1 = __half22float2(*reinterpret_cast<__half2*>(&m.y));
            float2 f2 = __half22float2(*reinterpret_cast<__half2*>(&m.z));
            float2 f3 = __half22float2(*reinterpret_cast<__half2*>(&m.w));
            a0 = fmaf(vj, f0.x, a0);  a1 = fmaf(vj, f0.y, a1);
            a2 = fmaf(vj, f1.x, a2);  a3 = fmaf(vj, f1.y, a3);
            a4 = fmaf(vj, f2.x, a4);  a5 = fmaf(vj, f2.y, a5);
            a6 = fmaf(vj, f3.x, a6);  a7 = fmaf(vj, f3.y, a7);
        }
    }

    // ---- tail strip (< 32 edges): guarded ----
    int rem = end - base;
    if (rem > 0) {
        int2 ep = make_int2(0, 0);
        if (lane < rem) ep = __ldg(edges + base + lane);
        #pragma unroll 4
        for (int j = 0; j < rem; j += 2) {
            int je = j + half;
            int coff = __shfl_sync(0xffffffffu, ep.x, je);
            int vb   = __shfl_sync(0xffffffffu, ep.y, je);
            if (je >= rem) { coff = 0; vb = 0; }    // zero-weight read of row 0
            float vj = __int_as_float(vb);
            uint4 m = __ldg(reinterpret_cast<const uint4*>(xb + coff));
            float2 f0 = __half22float2(*reinterpret_cast<__half2*>(&m.x));
            float2 f1 = __half22float2(*reinterpret_cast<__half2*>(&m.y));
            float2 f2 = __half22float2(*reinterpret_cast<__half2*>(&m.z));
            float2 f3 = __half22float2(*reinterpret_cast<__half2*>(&m.w));
            a0 = fmaf(vj, f0.x, a0);  a1 = fmaf(vj, f0.y, a1);
            a2 = fmaf(vj, f1.x, a2);  a3 = fmaf(vj, f1.y, a3);
            a4 = fmaf(vj, f2.x, a4);  a5 = fmaf(vj, f2.y, a5);
            a6 = fmaf(vj, f3.x, a6);  a7 = fmaf(vj, f3.y, a7);
        }
    }

    a0 += __shfl_xor_sync(0xffffffffu, a0, 16);
    a1 += __shfl_xor_sync(0xffffffffu, a1, 16);
    a2 += __shfl_xor_sync(0xffffffffu, a2, 16);
    a3 += __shfl_xor_sync(0xffffffffu, a3, 16);
    a4 += __shfl_xor_sync(0xffffffffu, a4, 16);
    a5 += __shfl_xor_sync(0xffffffffu, a5, 16);
    a6 += __shfl_xor_sync(0xffffffffu, a6, 16);
    a7 += __shfl_xor_sync(0xffffffffu, a7, 16);

    if (half == 0) {
        if (OUT_HALF) {
            __half2 h0 = __float22half2_rn(make_float2(a0, a1));
            __half2 h1 = __float22half2_rn(make_float2(a2, a3));
            __half2 h2 = __float22half2_rn(make_float2(a4, a5));
            __half2 h3 = __float22half2_rn(make_float2(a6, a7));
            uint4 o;
            o.x = *reinterpret_cast<unsigned*>(&h0);
            o.y = *reinterpret_cast<unsigned*>(&h1);
            o.z = *reinterpret_cast<unsigned*>(&h2);
            o.w = *reinterpret_cast<unsigned*>(&h3);
            reinterpret_cast<uint4*>(out)[(size_t)row * NH4 + hlane] = o;
        } else {
            float4* o4 = reinterpret_cast<float4*>(out) + (size_t)row * (D_FEAT / 4) + hlane * 2;
            o4[0] = make_float4(a0, a1, a2, a3);
            o4[1] = make_float4(a4, a5, a6, a7);
        }
    }
}

// ---------------- launch ----------------
extern "C" void kernel_launch(void* const* d_in, const int* in_sizes, int n_in,
                              void* d_out, int out_size) {
    const float* x        = (const float*)d_in[0];
    const int*   adj_row  = (const int*)  d_in[1];
    const int*   adj_col  = (const int*)  d_in[2];
    const float* adj_vals = (const float*)d_in[3];
    float*       out      = (float*)d_out;

    int n_edges = in_sizes[1];
    int n_q = n_edges / 4;             // int4 quads

    uint4 *xh, *scratchh; int *counts, *row_ptr, *cursor, *partials; int2 *edges;
    cudaGetSymbolAddress((void**)&xh,       g_xh);
    cudaGetSymbolAddress((void**)&scratchh, g_scratchh);
    cudaGetSymbolAddress((void**)&counts,   g_counts);
    cudaGetSymbolAddress((void**)&row_ptr,  g_row_ptr);
    cudaGetSymbolAddress((void**)&cursor,   g_cursor);
    cudaGetSymbolAddress((void**)&partials, g_partials);
    cudaGetSymbolAddress((void**)&edges,    g_edges);

    const int T = 256;
    const int histB = (n_q + 1 + T - 1) / T;   // +1 thread for the tail
    const int nconv = N_NODES * NH4;
    const int convB = (nconv + T - 1) / T;

    // Fused: histogram (RED) + fp16 conversion. counts zero at entry.
    hist_conv_kernel<<<histB + convB, T>>>((const int4*)adj_row, counts,
                                           n_q, n_edges, adj_row, histB,
                                           (const float4*)x, xh, nconv);

    scan_block_kernel<<<SCAN_BLOCKS, SCAN_CHUNK>>>(counts, row_ptr, cursor, partials);

    scatter_kernel<<<histB, T>>>((const int4*)adj_row, (const int4*)adj_col,
                                 (const float4*)adj_vals, cursor, partials,
                                 edges, n_q, n_edges,
                                 adj_row, adj_col, adj_vals);

    // Two propagation rounds.
    const int WPB = T / 32;
    const int sb = (N_NODES + WPB - 1) / WPB;
    spmm_csr_h_kernel<1><<<sb, T>>>(xh, row_ptr, partials, edges, scratchh);
    spmm_csr_h_kernel<0><<<sb, T>>>(scratchh, row_ptr, partials, edges, out);
}